// round 11
// baseline (speedup 1.0000x reference)
#include <cuda_runtime.h>
#include <cuda_fp16.h>
#include <cstdint>
#include <math.h>

// Flash attention, causal, B=2 H=16 S=2048 D=64, fp32 in/out.
// R8: R6 (256 thr/CTA, 8 warps x 16 q-rows, cp.async double-buffered raw K/V)
// with the V staging ownership FIXED to match the converter (cp.async
// visibility: a thread may only read its OWN async copies without a barrier).

#define SEQ 2048
#define DH  64
#define BQ  128
#define BK  64
#define NBH 32

// byte offsets in dynamic smem
#define OFF_K0 0                    // raw K fp32 (16384 B)
#define OFF_K1 16384
#define OFF_V0 32768                // raw V fp32, stride 272 B (17408 B)
#define OFF_V1 50176
#define OFF_KS 67584                // K fp16 [64][72h]  (9216 B)
#define OFF_VT 76800                // Vt fp16 [64][72h] (9216 B)
#define OFF_P  86016                // P fp16 [128][72h] (18432 B)
#define SMEM_TOTAL 104448

#define VRAW_STRIDE_B 272

__device__ __forceinline__ uint32_t s2u(const void* p) {
    uint32_t a;
    asm("{ .reg .u64 t; cvta.to.shared.u64 t, %1; cvt.u32.u64 %0, t; }" : "=r"(a) : "l"(p));
    return a;
}
__device__ __forceinline__ uint32_t pack2(float x, float y) {
    __half2 h = __floats2half2_rn(x, y);
    return *reinterpret_cast<uint32_t*>(&h);
}
__device__ __forceinline__ void cpa16(uint32_t dst, const void* src) {
    asm volatile("cp.async.cg.shared.global [%0], [%1], 16;" :: "r"(dst), "l"(src));
}
__device__ __forceinline__ void mma_f16(float c[4], const uint32_t a[4],
                                        uint32_t b0, uint32_t b1) {
    asm volatile(
        "mma.sync.aligned.m16n8k16.row.col.f32.f16.f16.f32 "
        "{%0,%1,%2,%3}, {%4,%5,%6,%7}, {%8,%9}, {%0,%1,%2,%3};"
        : "+f"(c[0]), "+f"(c[1]), "+f"(c[2]), "+f"(c[3])
        : "r"(a[0]), "r"(a[1]), "r"(a[2]), "r"(a[3]), "r"(b0), "r"(b1));
}

// Stage one K,V tile (fp32) via cp.async; ownership == converter ownership.
__device__ __forceinline__ void stage_kv(uint32_t sb, int buf,
                                         const float* __restrict__ Kg,
                                         const float* __restrict__ Vg,
                                         int tid, int wid, int lane) {
    uint32_t kdst = sb + (buf ? OFF_K1 : OFF_K0);
    #pragma unroll
    for (int i = 0; i < 4; i++) {
        int idx = tid + i * 256;                 // 16B chunk, 0..1023 (own chunks)
        cpa16(kdst + idx * 16, Kg + idx * 4);
    }
    // V: thread (wid,lane) stages rows 2*lane, 2*lane+1, chunks 2*wid, 2*wid+1
    // (exactly what its converter reads).
    uint32_t vdst = sb + (buf ? OFF_V1 : OFF_V0);
    #pragma unroll
    for (int a = 0; a < 2; a++) {
        int row = 2 * lane + a;
        #pragma unroll
        for (int dd = 0; dd < 2; dd++) {
            int c = 2 * wid + dd;                // 16B chunk within row
            cpa16(vdst + row * VRAW_STRIDE_B + c * 16, Vg + row * DH + c * 4);
        }
    }
}

__global__ __launch_bounds__(256, 2)
void fa_f16_kernel(const float* __restrict__ Q, const float* __restrict__ K,
                   const float* __restrict__ V, const int* __restrict__ causal_p,
                   const float* __restrict__ scale_p, float* __restrict__ Out) {
    extern __shared__ char smem[];
    const uint32_t sb = s2u(smem);

    uint32_t* Ksw = reinterpret_cast<uint32_t*>(smem + OFF_KS);  // stride 36 words
    uint32_t* Vtw = reinterpret_cast<uint32_t*>(smem + OFF_VT);  // stride 36 words

    const int tid  = threadIdx.x;
    const int wid  = tid >> 5;
    const int lane = tid & 31;
    const int bh   = blockIdx.y;
    const int n_qtiles = SEQ / BQ;
    const int qtile = n_qtiles - 1 - blockIdx.x;   // heavy causal tiles first
    const int q0 = qtile * BQ;
    const size_t base = (size_t)bh * SEQ * DH;
    const int causal = *causal_p;
    const float qscale = (*scale_p) * 1.4426950408889634f;

    const int r0 = q0 + wid * 16 + (lane >> 2);    // this lane's q rows
    const int r1 = r0 + 8;

    // ---- Prefetch tile 0 ---------------------------------------------------
    stage_kv(sb, 0, K + base, V + base, tid, wid, lane);
    asm volatile("cp.async.commit_group;" ::: "memory");

    // ---- Q fragments (pre-scaled fp16), 4 k16-steps ------------------------
    uint32_t qf[4][4];
    {
        const float* p0 = Q + base + (size_t)r0 * DH;
        const float* p1 = Q + base + (size_t)r1 * DH;
        #pragma unroll
        for (int kk = 0; kk < 4; kk++) {
            int d0 = kk * 16 + 2 * (lane & 3);
            float2 a0 = *reinterpret_cast<const float2*>(p0 + d0);
            float2 a1 = *reinterpret_cast<const float2*>(p1 + d0);
            float2 a2 = *reinterpret_cast<const float2*>(p0 + d0 + 8);
            float2 a3 = *reinterpret_cast<const float2*>(p1 + d0 + 8);
            qf[kk][0] = pack2(a0.x * qscale, a0.y * qscale);
            qf[kk][1] = pack2(a1.x * qscale, a1.y * qscale);
            qf[kk][2] = pack2(a2.x * qscale, a2.y * qscale);
            qf[kk][3] = pack2(a3.x * qscale, a3.y * qscale);
        }
    }

    float o[8][4];
    #pragma unroll
    for (int n = 0; n < 8; n++) { o[n][0]=0.f; o[n][1]=0.f; o[n][2]=0.f; o[n][3]=0.f; }
    float m0 = -INFINITY, m1 = -INFINITY, l0 = 0.f, l1 = 0.f;

    const int ntiles = causal ? (2 * qtile + 2) : (SEQ / BK);

    for (int t = 0; t < ntiles; t++) {
        const int kb = t * BK;
        const int buf = t & 1;

        // ---- Prefetch t+1, wait for t's raw data ---------------------------
        if (t + 1 < ntiles) {
            stage_kv(sb, buf ^ 1,
                     K + base + (size_t)(kb + BK) * DH,
                     V + base + (size_t)(kb + BK) * DH, tid, wid, lane);
            asm volatile("cp.async.commit_group;" ::: "memory");
            asm volatile("cp.async.wait_group 1;" ::: "memory");
        } else {
            asm volatile("cp.async.wait_group 0;" ::: "memory");
        }

        // ---- Convert own K chunks -> Ks fp16 -------------------------------
        {
            const char* kraw = smem + (buf ? OFF_K1 : OFF_K0);
            #pragma unroll
            for (int i = 0; i < 4; i++) {
                int idx = tid + i * 256;
                int row = idx >> 4, c4 = idx & 15;
                float4 v = *reinterpret_cast<const float4*>(kraw + idx * 16);
                uint2 h;
                h.x = pack2(v.x, v.y);
                h.y = pack2(v.z, v.w);
                *reinterpret_cast<uint2*>(smem + OFF_KS + row * 144 + c4 * 8) = h;
            }
        }
        // ---- Transpose own V chunks -> Vt fp16 (warp owns 8 dims) ----------
        {
            const char* vraw = smem + (buf ? OFF_V1 : OFF_V0);
            #pragma unroll
            for (int dd = 0; dd < 2; dd++) {
                int d0 = wid * 8 + dd * 4;
                float4 va = *reinterpret_cast<const float4*>(
                    vraw + (2 * lane)     * VRAW_STRIDE_B + d0 * 4);
                float4 vb = *reinterpret_cast<const float4*>(
                    vraw + (2 * lane + 1) * VRAW_STRIDE_B + d0 * 4);
                const float* pa = &va.x;
                const float* pb = &vb.x;
                #pragma unroll
                for (int j = 0; j < 4; j++)
                    Vtw[(d0 + j) * 36 + lane] = pack2(pa[j], pb[j]);
            }
        }
        __syncthreads();

        // ---- S = Q K^T  (m16 x n64 x k64 per warp) -------------------------
        float c[8][4];
        #pragma unroll
        for (int n = 0; n < 8; n++) {
            c[n][0]=0.f; c[n][1]=0.f; c[n][2]=0.f; c[n][3]=0.f;
            int key = n * 8 + (lane >> 2);
            #pragma unroll
            for (int kk = 0; kk < 4; kk++) {
                int dw = kk * 8 + (lane & 3);
                uint32_t b0 = Ksw[key * 36 + dw];
                uint32_t b1 = Ksw[key * 36 + dw + 4];
                mma_f16(c[n], qf[kk], b0, b1);
            }
        }

        // ---- Causal mask ---------------------------------------------------
        if (causal && (kb + BK - 1 > q0)) {
            #pragma unroll
            for (int n = 0; n < 8; n++) {
                int colb = kb + n * 8 + 2 * (lane & 3);
                if (colb     > r0) c[n][0] = -1e30f;
                if (colb + 1 > r0) c[n][1] = -1e30f;
                if (colb     > r1) c[n][2] = -1e30f;
                if (colb + 1 > r1) c[n][3] = -1e30f;
            }
        }

        // ---- Online softmax (log2 domain) ----------------------------------
        {
            float mr0 = -1e30f, mr1 = -1e30f;
            #pragma unroll
            for (int n = 0; n < 8; n++) {
                mr0 = fmaxf(mr0, fmaxf(c[n][0], c[n][1]));
                mr1 = fmaxf(mr1, fmaxf(c[n][2], c[n][3]));
            }
            mr0 = fmaxf(mr0, __shfl_xor_sync(0xffffffffu, mr0, 1));
            mr0 = fmaxf(mr0, __shfl_xor_sync(0xffffffffu, mr0, 2));
            mr1 = fmaxf(mr1, __shfl_xor_sync(0xffffffffu, mr1, 1));
            mr1 = fmaxf(mr1, __shfl_xor_sync(0xffffffffu, mr1, 2));
            float mn0 = fmaxf(m0, mr0);
            float mn1 = fmaxf(m1, mr1);
            float sf0 = exp2f(m0 - mn0);
            float sf1 = exp2f(m1 - mn1);
            m0 = mn0; m1 = mn1;

            float s0 = 0.f, s1 = 0.f;
            #pragma unroll
            for (int n = 0; n < 8; n++) {
                c[n][0] = exp2f(c[n][0] - mn0);
                c[n][1] = exp2f(c[n][1] - mn0);
                c[n][2] = exp2f(c[n][2] - mn1);
                c[n][3] = exp2f(c[n][3] - mn1);
                s0 += c[n][0] + c[n][1];
                s1 += c[n][2] + c[n][3];
            }
            s0 += __shfl_xor_sync(0xffffffffu, s0, 1);
            s0 += __shfl_xor_sync(0xffffffffu, s0, 2);
            s1 += __shfl_xor_sync(0xffffffffu, s1, 1);
            s1 += __shfl_xor_sync(0xffffffffu, s1, 2);
            l0 = l0 * sf0 + s0;
            l1 = l1 * sf1 + s1;
            #pragma unroll
            for (int n = 0; n < 8; n++) {
                o[n][0] *= sf0; o[n][1] *= sf0;
                o[n][2] *= sf1; o[n][3] *= sf1;
            }
        }

        // ---- Stage P fp16 (warp-private 16 rows) ---------------------------
        uint32_t* Pw = reinterpret_cast<uint32_t*>(smem + OFF_P + wid * 16 * 144);
        {
            int rr = lane >> 2;
            #pragma unroll
            for (int n = 0; n < 8; n++) {
                int colw = n * 4 + (lane & 3);
                Pw[rr       * 36 + colw] = pack2(c[n][0], c[n][1]);
                Pw[(rr + 8) * 36 + colw] = pack2(c[n][2], c[n][3]);
            }
        }
        __syncwarp();

        // ---- O += P V  (m16 x n64 x k64 per warp) --------------------------
        #pragma unroll
        for (int kk = 0; kk < 4; kk++) {
            uint32_t a[4];
            int rr = lane >> 2;
            int kw = kk * 8 + (lane & 3);
            a[0] = Pw[rr       * 36 + kw];
            a[1] = Pw[(rr + 8) * 36 + kw];
            a[2] = Pw[rr       * 36 + kw + 4];
            a[3] = Pw[(rr + 8) * 36 + kw + 4];
            #pragma unroll
            for (int n = 0; n < 8; n++) {
                int dim = n * 8 + (lane >> 2);
                uint32_t b0 = Vtw[dim * 36 + kw];
                uint32_t b1 = Vtw[dim * 36 + kw + 4];
                mma_f16(o[n], a, b0, b1);
            }
        }
        __syncthreads();   // protect Ks/Vt before next tile's convert
    }

    // ---- Epilogue ----------------------------------------------------------
    float* op = Out + base;
    {
        float inv0 = 1.f / l0;
        float inv1 = 1.f / l1;
        #pragma unroll
        for (int n = 0; n < 8; n++) {
            int col = n * 8 + 2 * (lane & 3);
            float2 v0 = make_float2(o[n][0] * inv0, o[n][1] * inv0);
            float2 v1 = make_float2(o[n][2] * inv1, o[n][3] * inv1);
            *reinterpret_cast<float2*>(&op[(size_t)r0 * DH + col]) = v0;
            *reinterpret_cast<float2*>(&op[(size_t)r1 * DH + col]) = v1;
        }
    }
}

extern "C" void kernel_launch(void* const* d_in, const int* in_sizes, int n_in,
                              void* d_out, int out_size) {
    const float* Q      = (const float*)d_in[0];
    const float* K      = (const float*)d_in[1];
    const float* V      = (const float*)d_in[2];
    const int*   causal = (const int*)d_in[3];
    const float* scale  = (const float*)d_in[4];
    float* out = (float*)d_out;

    cudaFuncSetAttribute(fa_f16_kernel,
                         cudaFuncAttributeMaxDynamicSharedMemorySize, SMEM_TOTAL);

    dim3 grid(SEQ / BQ, NBH);   // 16 x 32 CTAs
    fa_f16_kernel<<<grid, 256, SMEM_TOTAL>>>(Q, K, V, causal, scale, out);
}

// round 12
// speedup vs baseline: 1.1966x; 1.1966x over previous
#include <cuda_runtime.h>
#include <cuda_fp16.h>
#include <cstdint>
#include <math.h>

// Flash attention, causal, B=2 H=16 S=2048 D=64, fp32 in/out.
// R11: 128 thr/CTA (4 warps x 32 q-rows), cp.async double-buffered raw K/V,
// double-buffered converted Ks/Vt, ONE __syncthreads per tile, and P kept in
// registers (S C-fragment == PV A-fragment for m16n8k16 -> no P staging).

#define SEQ 2048
#define DH  64
#define BQ  128
#define BK  64
#define NBH 32

// byte offsets in dynamic smem
#define OFF_K0  0                   // raw K fp32 (16384 B)
#define OFF_K1  16384
#define OFF_V0  32768               // raw V fp32, stride 272 B (17408 B)
#define OFF_V1  50176
#define OFF_KS0 67584               // K fp16 [64][72h] (9216 B)
#define OFF_KS1 76800
#define OFF_VT0 86016               // Vt fp16 [64][72h] (9216 B)
#define OFF_VT1 95232
#define SMEM_TOTAL 104448

#define VRAW_STRIDE_B 272

__device__ __forceinline__ uint32_t s2u(const void* p) {
    uint32_t a;
    asm("{ .reg .u64 t; cvta.to.shared.u64 t, %1; cvt.u32.u64 %0, t; }" : "=r"(a) : "l"(p));
    return a;
}
__device__ __forceinline__ uint32_t pack2(float x, float y) {
    __half2 h = __floats2half2_rn(x, y);
    return *reinterpret_cast<uint32_t*>(&h);
}
__device__ __forceinline__ void cpa16(uint32_t dst, const void* src) {
    asm volatile("cp.async.cg.shared.global [%0], [%1], 16;" :: "r"(dst), "l"(src));
}
__device__ __forceinline__ void mma_f16(float c[4], const uint32_t a[4],
                                        uint32_t b0, uint32_t b1) {
    asm volatile(
        "mma.sync.aligned.m16n8k16.row.col.f32.f16.f16.f32 "
        "{%0,%1,%2,%3}, {%4,%5,%6,%7}, {%8,%9}, {%0,%1,%2,%3};"
        : "+f"(c[0]), "+f"(c[1]), "+f"(c[2]), "+f"(c[3])
        : "r"(a[0]), "r"(a[1]), "r"(a[2]), "r"(a[3]), "r"(b0), "r"(b1));
}

// Stage one K,V fp32 tile via cp.async; ownership == converter ownership.
__device__ __forceinline__ void stage_kv(uint32_t sb, int buf,
                                         const float* __restrict__ Kg,
                                         const float* __restrict__ Vg,
                                         int tid, int wid, int lane) {
    uint32_t kdst = sb + (buf ? OFF_K1 : OFF_K0);
    #pragma unroll
    for (int i = 0; i < 8; i++) {
        int idx = tid + i * 128;                 // 16B chunk, 0..1023 (own)
        cpa16(kdst + idx * 16, Kg + idx * 4);
    }
    // V: thread (wid,lane) stages rows 2*lane, 2*lane+1, chunks wid*4+dd
    // (exactly what its converter reads).
    uint32_t vdst = sb + (buf ? OFF_V1 : OFF_V0);
    #pragma unroll
    for (int a = 0; a < 2; a++) {
        int row = 2 * lane + a;
        #pragma unroll
        for (int dd = 0; dd < 4; dd++) {
            int colf = wid * 16 + dd * 4;
            cpa16(vdst + row * VRAW_STRIDE_B + colf * 4, Vg + row * DH + colf);
        }
    }
}

__global__ __launch_bounds__(128, 2)
void fa_f16_kernel(const float* __restrict__ Q, const float* __restrict__ K,
                   const float* __restrict__ V, const int* __restrict__ causal_p,
                   const float* __restrict__ scale_p, float* __restrict__ Out) {
    extern __shared__ char smem[];
    const uint32_t sb = s2u(smem);

    const int tid  = threadIdx.x;
    const int wid  = tid >> 5;
    const int lane = tid & 31;
    const int bh   = blockIdx.y;
    const int n_qtiles = SEQ / BQ;
    const int qtile = n_qtiles - 1 - blockIdx.x;   // heavy causal tiles first
    const int q0 = qtile * BQ;
    const size_t base = (size_t)bh * SEQ * DH;
    const int causal = *causal_p;
    const float qscale = (*scale_p) * 1.4426950408889634f;

    int r[2][2];
    #pragma unroll
    for (int rb = 0; rb < 2; rb++) {
        r[rb][0] = q0 + wid * 32 + rb * 16 + (lane >> 2);
        r[rb][1] = r[rb][0] + 8;
    }

    // ---- Prefetch tile 0 ---------------------------------------------------
    stage_kv(sb, 0, K + base, V + base, tid, wid, lane);
    asm volatile("cp.async.commit_group;" ::: "memory");

    // ---- Q fragments (pre-scaled fp16), 4 k16-steps ------------------------
    uint32_t qf[2][4][4];
    {
        const float* qp = Q + base;
        #pragma unroll
        for (int rb = 0; rb < 2; rb++)
            #pragma unroll
            for (int kk = 0; kk < 4; kk++) {
                int d0 = kk * 16 + 2 * (lane & 3);
                const float* p0 = qp + (size_t)r[rb][0] * DH;
                const float* p1 = qp + (size_t)r[rb][1] * DH;
                float2 a0 = *reinterpret_cast<const float2*>(p0 + d0);
                float2 a1 = *reinterpret_cast<const float2*>(p1 + d0);
                float2 a2 = *reinterpret_cast<const float2*>(p0 + d0 + 8);
                float2 a3 = *reinterpret_cast<const float2*>(p1 + d0 + 8);
                qf[rb][kk][0] = pack2(a0.x * qscale, a0.y * qscale);
                qf[rb][kk][1] = pack2(a1.x * qscale, a1.y * qscale);
                qf[rb][kk][2] = pack2(a2.x * qscale, a2.y * qscale);
                qf[rb][kk][3] = pack2(a3.x * qscale, a3.y * qscale);
            }
    }

    float o[2][8][4];
    #pragma unroll
    for (int rb = 0; rb < 2; rb++)
        #pragma unroll
        for (int n = 0; n < 8; n++) {
            o[rb][n][0]=0.f; o[rb][n][1]=0.f; o[rb][n][2]=0.f; o[rb][n][3]=0.f;
        }
    float m[2][2] = {{-INFINITY, -INFINITY}, {-INFINITY, -INFINITY}};
    float l[2][2] = {{0.f, 0.f}, {0.f, 0.f}};

    const int ntiles = causal ? (2 * qtile + 2) : (SEQ / BK);

    for (int t = 0; t < ntiles; t++) {
        const int kb = t * BK;
        const int buf = t & 1;

        // ---- Prefetch t+1, wait for t's raw data ---------------------------
        if (t + 1 < ntiles) {
            stage_kv(sb, buf ^ 1,
                     K + base + (size_t)(kb + BK) * DH,
                     V + base + (size_t)(kb + BK) * DH, tid, wid, lane);
            asm volatile("cp.async.commit_group;" ::: "memory");
            asm volatile("cp.async.wait_group 1;" ::: "memory");
        } else {
            asm volatile("cp.async.wait_group 0;" ::: "memory");
        }

        uint32_t* Ksw = reinterpret_cast<uint32_t*>(smem + (buf ? OFF_KS1 : OFF_KS0));
        uint32_t* Vtw = reinterpret_cast<uint32_t*>(smem + (buf ? OFF_VT1 : OFF_VT0));

        // ---- Convert own K chunks -> Ks[buf] fp16 --------------------------
        {
            const char* kraw = smem + (buf ? OFF_K1 : OFF_K0);
            char* ksd = smem + (buf ? OFF_KS1 : OFF_KS0);
            #pragma unroll
            for (int i = 0; i < 8; i++) {
                int idx = tid + i * 128;
                int row = idx >> 4, c4 = idx & 15;
                float4 v = *reinterpret_cast<const float4*>(kraw + idx * 16);
                uint2 h;
                h.x = pack2(v.x, v.y);
                h.y = pack2(v.z, v.w);
                *reinterpret_cast<uint2*>(ksd + row * 144 + c4 * 8) = h;
            }
        }
        // ---- Transpose own V chunks -> Vt[buf] fp16 ------------------------
        {
            const char* vraw = smem + (buf ? OFF_V1 : OFF_V0);
            float4 va[4], vb[4];
            #pragma unroll
            for (int dd = 0; dd < 4; dd++) {
                int colb = (wid * 16 + dd * 4) * 4;
                va[dd] = *reinterpret_cast<const float4*>(vraw + (2 * lane)     * VRAW_STRIDE_B + colb);
                vb[dd] = *reinterpret_cast<const float4*>(vraw + (2 * lane + 1) * VRAW_STRIDE_B + colb);
            }
            #pragma unroll
            for (int dd = 0; dd < 4; dd++) {
                int d0 = wid * 16 + dd * 4;
                const float* pa = &va[dd].x;
                const float* pb = &vb[dd].x;
                #pragma unroll
                for (int j = 0; j < 4; j++)
                    Vtw[(d0 + j) * 36 + lane] = pack2(pa[j], pb[j]);
            }
        }
        __syncthreads();   // the ONLY barrier per tile

        // ---- S = Q K^T  (m32 x n64 x k64 per warp) -------------------------
        float c[2][8][4];
        #pragma unroll
        for (int n = 0; n < 8; n++) {
            #pragma unroll
            for (int rb = 0; rb < 2; rb++) {
                c[rb][n][0]=0.f; c[rb][n][1]=0.f; c[rb][n][2]=0.f; c[rb][n][3]=0.f;
            }
            int key = n * 8 + (lane >> 2);
            #pragma unroll
            for (int kk = 0; kk < 4; kk++) {
                int dw = kk * 8 + (lane & 3);
                uint32_t b0 = Ksw[key * 36 + dw];
                uint32_t b1 = Ksw[key * 36 + dw + 4];
                mma_f16(c[0][n], qf[0][kk], b0, b1);
                mma_f16(c[1][n], qf[1][kk], b0, b1);
            }
        }

        // ---- Causal mask ---------------------------------------------------
        if (causal && (kb + BK - 1 > q0)) {
            #pragma unroll
            for (int rb = 0; rb < 2; rb++)
                #pragma unroll
                for (int n = 0; n < 8; n++) {
                    int colb = kb + n * 8 + 2 * (lane & 3);
                    if (colb     > r[rb][0]) c[rb][n][0] = -1e30f;
                    if (colb + 1 > r[rb][0]) c[rb][n][1] = -1e30f;
                    if (colb     > r[rb][1]) c[rb][n][2] = -1e30f;
                    if (colb + 1 > r[rb][1]) c[rb][n][3] = -1e30f;
                }
        }

        // ---- Online softmax (log2 domain) ----------------------------------
        float sf[2][2];
        #pragma unroll
        for (int rb = 0; rb < 2; rb++) {
            float mr0 = -1e30f, mr1 = -1e30f;
            #pragma unroll
            for (int n = 0; n < 8; n++) {
                mr0 = fmaxf(mr0, fmaxf(c[rb][n][0], c[rb][n][1]));
                mr1 = fmaxf(mr1, fmaxf(c[rb][n][2], c[rb][n][3]));
            }
            mr0 = fmaxf(mr0, __shfl_xor_sync(0xffffffffu, mr0, 1));
            mr0 = fmaxf(mr0, __shfl_xor_sync(0xffffffffu, mr0, 2));
            mr1 = fmaxf(mr1, __shfl_xor_sync(0xffffffffu, mr1, 1));
            mr1 = fmaxf(mr1, __shfl_xor_sync(0xffffffffu, mr1, 2));
            float mn0 = fmaxf(m[rb][0], mr0);
            float mn1 = fmaxf(m[rb][1], mr1);
            sf[rb][0] = exp2f(m[rb][0] - mn0);
            sf[rb][1] = exp2f(m[rb][1] - mn1);
            m[rb][0] = mn0; m[rb][1] = mn1;

            float s0 = 0.f, s1 = 0.f;
            #pragma unroll
            for (int n = 0; n < 8; n++) {
                c[rb][n][0] = exp2f(c[rb][n][0] - mn0);
                c[rb][n][1] = exp2f(c[rb][n][1] - mn0);
                c[rb][n][2] = exp2f(c[rb][n][2] - mn1);
                c[rb][n][3] = exp2f(c[rb][n][3] - mn1);
                s0 += c[rb][n][0] + c[rb][n][1];
                s1 += c[rb][n][2] + c[rb][n][3];
            }
            s0 += __shfl_xor_sync(0xffffffffu, s0, 1);
            s0 += __shfl_xor_sync(0xffffffffu, s0, 2);
            s1 += __shfl_xor_sync(0xffffffffu, s1, 1);
            s1 += __shfl_xor_sync(0xffffffffu, s1, 2);
            l[rb][0] = l[rb][0] * sf[rb][0] + s0;
            l[rb][1] = l[rb][1] * sf[rb][1] + s1;
            #pragma unroll
            for (int n = 0; n < 8; n++) {
                o[rb][n][0] *= sf[rb][0]; o[rb][n][1] *= sf[rb][0];
                o[rb][n][2] *= sf[rb][1]; o[rb][n][3] *= sf[rb][1];
            }
        }

        // ---- O += P V: A-fragment IS the S C-fragment (registers, no smem) -
        #pragma unroll
        for (int kk = 0; kk < 4; kk++) {
            uint32_t a[2][4];
            #pragma unroll
            for (int rb = 0; rb < 2; rb++) {
                a[rb][0] = pack2(c[rb][2 * kk][0],     c[rb][2 * kk][1]);
                a[rb][1] = pack2(c[rb][2 * kk][2],     c[rb][2 * kk][3]);
                a[rb][2] = pack2(c[rb][2 * kk + 1][0], c[rb][2 * kk + 1][1]);
                a[rb][3] = pack2(c[rb][2 * kk + 1][2], c[rb][2 * kk + 1][3]);
            }
            int kw = kk * 8 + (lane & 3);
            #pragma unroll
            for (int n = 0; n < 8; n++) {
                int dim = n * 8 + (lane >> 2);
                uint32_t b0 = Vtw[dim * 36 + kw];
                uint32_t b1 = Vtw[dim * 36 + kw + 4];
                mma_f16(o[0][n], a[0], b0, b1);
                mma_f16(o[1][n], a[1], b0, b1);
            }
        }
        // no end-of-tile barrier: next tile converts into the OTHER Ks/Vt buf
    }

    // ---- Epilogue ----------------------------------------------------------
    float* op = Out + base;
    #pragma unroll
    for (int rb = 0; rb < 2; rb++) {
        float inv0 = 1.f / l[rb][0];
        float inv1 = 1.f / l[rb][1];
        #pragma unroll
        for (int n = 0; n < 8; n++) {
            int col = n * 8 + 2 * (lane & 3);
            float2 v0 = make_float2(o[rb][n][0] * inv0, o[rb][n][1] * inv0);
            float2 v1 = make_float2(o[rb][n][2] * inv1, o[rb][n][3] * inv1);
            *reinterpret_cast<float2*>(&op[(size_t)r[rb][0] * DH + col]) = v0;
            *reinterpret_cast<float2*>(&op[(size_t)r[rb][1] * DH + col]) = v1;
        }
    }
}

extern "C" void kernel_launch(void* const* d_in, const int* in_sizes, int n_in,
                              void* d_out, int out_size) {
    const float* Q      = (const float*)d_in[0];
    const float* K      = (const float*)d_in[1];
    const float* V      = (const float*)d_in[2];
    const int*   causal = (const int*)d_in[3];
    const float* scale  = (const float*)d_in[4];
    float* out = (float*)d_out;

    cudaFuncSetAttribute(fa_f16_kernel,
                         cudaFuncAttributeMaxDynamicSharedMemorySize, SMEM_TOTAL);

    dim3 grid(SEQ / BQ, NBH);   // 16 x 32 CTAs
    fa_f16_kernel<<<grid, 128, SMEM_TOTAL>>>(Q, K, V, causal, scale, out);
}